// round 1
// baseline (speedup 1.0000x reference)
#include <cuda_runtime.h>

//
// Morphological skeleton, fused-iteration kernel for GB300 (sm_103a).
//
// reference:  skel = sum_{j=0..20} ( x_j - dilate3(erode3(x_j)) ),  x_{j+1} = erode3(x_j)
// where erode3/dilate3 are 3x3 min/max with border clipping (SAME, -inf pad).
//
// Strategy: fuse K iterations per launch in shared memory with halo H = K+1.
//   launch 1: K=11, reads input x, writes x_11 to scratch, writes skel (init)
//   launch 2: K=10, reads scratch,  accumulates into skel
// Tile: 128x128 interior, halo 12 -> 152x152 region, two smem buffers (ping-pong),
// 184,832 B dynamic smem, 512 threads, 1 CTA/SM.
//
// Border handling: region loads clamp to image (replicate). Replicated / stale
// out-of-image cells are always >= the true clipped erosion values, so they are
// harmless under min (erode). They are NOT harmless under max (dilate), so edge
// blocks rewrite the 1-cell ring around the interior with exact boundary
// replicas of e after each erode pass, before the dilate pass.
//

#define IMG      1024
#define NIMG     16
#define TILE     128
#define HALO     12
#define RW       (TILE + 2*HALO)          /* 152 */
#define RSZ      (RW*RW)                  /* 23104 */
#define NQ       (RW/4)                   /* 38 float4 columns */
#define NTHREADS 512
#define ESH      13                       /* erode strip height */
#define ENSTRIP  ((RW + ESH - 1) / ESH)   /* 12 */
#define EUNITS   (NQ * ENSTRIP)           /* 456 */
#define SMEM_BYTES (2 * RSZ * 4)          /* 184832 */

__device__ float g_scratch[(size_t)NIMG * IMG * IMG];

__device__ __forceinline__ float min3f(float a, float b, float c) { return fminf(fminf(a, b), c); }
__device__ __forceinline__ float max3f(float a, float b, float c) { return fmaxf(fmaxf(a, b), c); }

__device__ __forceinline__ float4 rowmin4(const float* row, int xb) {
    float4 v = *(const float4*)(row + xb);
    float l = (xb > 0)      ? row[xb - 1] : v.x;   // replicate at region edge (min-safe)
    float r = (xb + 4 < RW) ? row[xb + 4] : v.w;
    float4 m;
    m.x = min3f(l,   v.x, v.y);
    m.y = min3f(v.x, v.y, v.z);
    m.z = min3f(v.y, v.z, v.w);
    m.w = min3f(v.z, v.w, r);
    return m;
}

__device__ __forceinline__ float4 rowmax4(const float* row) {
    // interior-only use: row points at (y*RW + ix); ix-1 >= 11 and ix+4 <= 140 always valid
    float4 v = *(const float4*)row;
    float l = row[-1];
    float r = row[4];
    float4 m;
    m.x = max3f(l,   v.x, v.y);
    m.y = max3f(v.x, v.y, v.z);
    m.z = max3f(v.y, v.z, v.w);
    m.w = max3f(v.z, v.w, r);
    return m;
}

__global__ void __launch_bounds__(NTHREADS, 1)
skel_fused_kernel(const float* __restrict__ xin,
                  float* __restrict__ xout,
                  float* __restrict__ skel,
                  int niter, int accum, int writex)
{
    extern __shared__ float smem[];
    float* P = smem;          // holds x_j
    float* Q = smem + RSZ;    // holds e = erode(x_j)

    const int tid = threadIdx.x;
    const int bx = blockIdx.x, by = blockIdx.y, bz = blockIdx.z;
    const int gx0 = bx * TILE - HALO;
    const int gy0 = by * TILE - HALO;
    const float* img = xin + (size_t)bz * IMG * IMG;

    // ---- load region with clamped (replicate) borders ----
    for (int i = tid; i < RSZ; i += NTHREADS) {
        int y = i / RW;
        int x = i - y * RW;
        int gy = gy0 + y; gy = gy < 0 ? 0 : (gy > IMG - 1 ? IMG - 1 : gy);
        int gx = gx0 + x; gx = gx < 0 ? 0 : (gx > IMG - 1 ? IMG - 1 : gx);
        P[i] = img[(size_t)gy * IMG + gx];
    }
    __syncthreads();

    const bool topE   = (by == 0);
    const bool botE   = (by == (int)gridDim.y - 1);
    const bool leftE  = (bx == 0);
    const bool rightE = (bx == (int)gridDim.x - 1);
    const bool anyE   = topE || botE || leftE || rightE;

    // erode-pass mapping: 38 float4 columns x 12 vertical strips of 13 rows
    const int eq  = tid % NQ;
    const int es  = tid / NQ;
    const int exb = eq * 4;
    const int esy = es * ESH;

    // dilate/interior mapping: 32 float4 columns x 16 strips of 8 rows
    const int qi = tid & 31;
    const int ry = (tid >> 5) * 8;
    const int ix = HALO + qi * 4;
    const int iy = HALO + ry;

    float4 acc[8];
#pragma unroll
    for (int k = 0; k < 8; k++) acc[k] = make_float4(0.f, 0.f, 0.f, 0.f);

    for (int it = 0; it < niter; it++) {
        // ---------- erode: Q = 3x3 min of P (full region, shrinking validity) ----------
        if (tid < EUNITS) {
            int yend = esy + ESH; if (yend > RW) yend = RW;
            int y0 = esy - 1; if (y0 < 0) y0 = 0;
            float4 rm0 = rowmin4(P + y0 * RW, exb);
            float4 rm1 = rowmin4(P + esy * RW, exb);
            for (int y = esy; y < yend; y++) {
                int yn = y + 1; if (yn > RW - 1) yn = RW - 1;
                float4 rm2 = rowmin4(P + yn * RW, exb);
                float4 o;
                o.x = min3f(rm0.x, rm1.x, rm2.x);
                o.y = min3f(rm0.y, rm1.y, rm2.y);
                o.z = min3f(rm0.z, rm1.z, rm2.z);
                o.w = min3f(rm0.w, rm1.w, rm2.w);
                *(float4*)(Q + y * RW + exb) = o;
                rm0 = rm1; rm1 = rm2;
            }
        }
        __syncthreads();

        // ---------- image-border fix-up of e ring (only edge blocks) ----------
        if (anyE) {
            if (tid < TILE + 2) {
                int o = HALO - 1 + tid;                 // 11 .. 140
                int sx = o;
                if (leftE  && sx < HALO)            sx = HALO;
                if (rightE && sx > HALO + TILE - 1) sx = HALO + TILE - 1;
                int sy = o;
                if (topE && sy < HALO)              sy = HALO;
                if (botE && sy > HALO + TILE - 1)   sy = HALO + TILE - 1;
                if (topE)   Q[(HALO - 1) * RW + o]        = Q[HALO * RW + sx];
                if (botE)   Q[(HALO + TILE) * RW + o]     = Q[(HALO + TILE - 1) * RW + sx];
                if (leftE)  Q[o * RW + (HALO - 1)]        = Q[sy * RW + HALO];
                if (rightE) Q[o * RW + (HALO + TILE)]     = Q[sy * RW + (HALO + TILE - 1)];
            }
            __syncthreads();
        }

        // ---------- dilate(e) at interior, accumulate skel += x_j - d ----------
        {
            float4 rm0 = rowmax4(Q + (iy - 1) * RW + ix);
            float4 rm1 = rowmax4(Q + iy * RW + ix);
#pragma unroll
            for (int k = 0; k < 8; k++) {
                float4 rm2 = rowmax4(Q + (iy + k + 1) * RW + ix);
                float4 xv = *(const float4*)(P + (iy + k) * RW + ix);
                acc[k].x += xv.x - max3f(rm0.x, rm1.x, rm2.x);
                acc[k].y += xv.y - max3f(rm0.y, rm1.y, rm2.y);
                acc[k].z += xv.z - max3f(rm0.z, rm1.z, rm2.z);
                acc[k].w += xv.w - max3f(rm0.w, rm1.w, rm2.w);
                rm0 = rm1; rm1 = rm2;
            }
        }
        __syncthreads();

        // ping-pong: e becomes next x
        float* t = P; P = Q; Q = t;
    }

    // ---------- write outputs ----------
    const int gxo = bx * TILE + qi * 4;
    const int gyo = by * TILE + ry;

    if (writex) {
        float* xo = xout + (size_t)bz * IMG * IMG;
#pragma unroll
        for (int k = 0; k < 8; k++)
            *(float4*)(xo + (size_t)(gyo + k) * IMG + gxo) =
                *(const float4*)(P + (iy + k) * RW + ix);
    }

    float* so = skel + (size_t)bz * IMG * IMG;
    if (accum) {
#pragma unroll
        for (int k = 0; k < 8; k++) {
            float4 s = *(const float4*)(so + (size_t)(gyo + k) * IMG + gxo);
            s.x += acc[k].x; s.y += acc[k].y; s.z += acc[k].z; s.w += acc[k].w;
            *(float4*)(so + (size_t)(gyo + k) * IMG + gxo) = s;
        }
    } else {
#pragma unroll
        for (int k = 0; k < 8; k++)
            *(float4*)(so + (size_t)(gyo + k) * IMG + gxo) = acc[k];
    }
}

extern "C" void kernel_launch(void* const* d_in, const int* in_sizes, int n_in,
                              void* d_out, int out_size)
{
    (void)in_sizes; (void)n_in; (void)out_size;
    const float* x = (const float*)d_in[0];
    float* skel = (float*)d_out;

    float* scratch = nullptr;
    cudaGetSymbolAddress((void**)&scratch, g_scratch);

    cudaFuncSetAttribute(skel_fused_kernel,
                         cudaFuncAttributeMaxDynamicSharedMemorySize, SMEM_BYTES);

    dim3 grid(IMG / TILE, IMG / TILE, NIMG);   // 8 x 8 x 16
    // iterations 0..10 (11 terms): init skel, write x_11 to scratch
    skel_fused_kernel<<<grid, NTHREADS, SMEM_BYTES>>>(x, scratch, skel, 11, 0, 1);
    // iterations 11..20 (10 terms): accumulate skel, no x output
    skel_fused_kernel<<<grid, NTHREADS, SMEM_BYTES>>>(scratch, scratch, skel, 10, 1, 0);
}